// round 17
// baseline (speedup 1.0000x reference)
#include <cuda_runtime.h>
#include <cuda_fp16.h>

// Problem constants
#define Bn 2
#define Ln 16
#define Cn 16
#define Hn 64
#define Wn 64
#define HW (Hn * Wn)            // 4096

// Padded transposed image, fp16: entry = 16 channels (32B).
// Rows cover y = -1..65 (PR=67), cols cover x = -1..64 (PC=66).
// Border entries are never written -> stay zero (device globals zero-init).
#define PR 67
#define PC 66
#define PLANE (PR * PC)         // 4422 entries per (b,l)

__device__ __half g_imgTh[Bn * Ln * PLANE * Cn];   // ~4.5 MB

static __device__ __forceinline__ unsigned pack_h2(float a, float b) {
    __half2 h = __floats2half2_rn(a, b);
    return *reinterpret_cast<unsigned*>(&h);
}

static __device__ __forceinline__ __half2 as_h2(unsigned u) {
    return *reinterpret_cast<const __half2*>(&u);
}

// ---------------------------------------------------------------------------
// Kernel 1: transpose images (B,L,C,H,W) -> padded fp16 (B,L,y,x,C).
// One thread per 8-channel half-pixel: 8 coalesced float loads, 1 uint4 store.
// ---------------------------------------------------------------------------
__global__ void __launch_bounds__(256) transpose_kernel(const float* __restrict__ images) {
    int t = blockIdx.x * blockDim.x + threadIdx.x;   // 0 .. 2*B*L*HW-1
    if (t >= 2 * Bn * Ln * HW) return;
    int half_id = t & 1;            // which 8 channels
    int pix = t >> 1;
    int hw = pix & (HW - 1);
    int bl = pix >> 12;
    int w = hw & (Wn - 1);
    int h = hw >> 6;

    const float* src = images + (size_t)bl * Cn * HW + (size_t)(half_id * 8) * HW + hw;
    float v[8];
#pragma unroll
    for (int c = 0; c < 8; c++) v[c] = src[(size_t)c * HW];

    size_t e = (size_t)bl * PLANE + (size_t)(h + 1) * PC + (w + 1);
    uint4* dst = reinterpret_cast<uint4*>(g_imgTh + e * Cn) + half_id;
    *dst = make_uint4(pack_h2(v[0], v[1]), pack_h2(v[2], v[3]),
                      pack_h2(v[4], v[5]), pack_h2(v[6], v[7]));
}

// ---------------------------------------------------------------------------
// Kernel 2: main (frozen structure: 4 lanes/pixel, unroll 2, LPT order,
// half2 blend + fp32 accumulation). NEW: flow cumsum for the block's 64
// pixels is computed once into smem; the j-loop reads cum[j] via LDS
// (broadcast, conflict-free) -> no global load in the loop-carried chain,
// iterations fully independent, 2 fewer global loads per j.
// ---------------------------------------------------------------------------
__global__ void __launch_bounds__(256) gridsample_pscan_kernel(const float* __restrict__ flows,
                                                               float* __restrict__ out) {
    __shared__ float s_cum[2][Ln][64];     // 8 KB

    const int bid = blockIdx.x;            // 0 .. 2047
    const int q   = bid >> 6;              // 0 .. 31
    const int b   = q & 1;
    const int i   = 15 - (q >> 1);         // heavy blocks first (LPT)
    const int tid = threadIdx.x;
    const int h   = bid & 63;              // tile = one image row
    const int hw0 = h << 6;

    // ---- Prologue: cumsum of flows for this row's 64 pixels ----
    if (tid < 128) {
        int d = tid >> 6;                  // 0: x, 1: y
        int p = tid & 63;
        const float* fp = flows + ((size_t)(b * Ln) * 2 + d) * HW + (hw0 + p);
        float f[Ln];
#pragma unroll
        for (int j = 0; j < Ln; j++) f[j] = fp[(size_t)(j * 2) * HW];  // independent, coalesced
        float a = 0.0f;
#pragma unroll
        for (int j = 0; j < Ln; j++) { a += f[j]; s_cum[d][j][p] = a; }
    }
    __syncthreads();

    const int cg = tid & 3;                // channel group (4 channels)
    const int p  = tid >> 2;               // pixel within row (== w)
    const int hw = hw0 | p;
    const int bi = (b << 4) | i;

    const float uxb = (float)p + 0.5f;
    const float fyb = (float)h;

    const float cix = s_cum[0][i][p];
    const float ciy = s_cum[1][i][p];

    const __half* imgb = g_imgTh + (size_t)b * Ln * PLANE * Cn + cg * 4;

    float acc0 = 0.0f, acc1 = 0.0f, acc2 = 0.0f, acc3 = 0.0f;

#pragma unroll 2
    for (int j = 0; j <= i; j++) {
        float relx = cix - s_cum[0][j][p];
        float rely = ciy - s_cum[1][j][p];

        // x: wrap into [0,64), then shift by -0.5
        float u  = fmaf(relx, 32.0f, uxb);
        float fq = floorf(u * 0.015625f);           // u/64
        float ix = fmaf(fq, -64.0f, u) - 0.5f;      // in [-0.5, 63.5)
        // y: clamp to [-1, 64] (== reference masking w/ zero border)
        float iy = fmaf(rely, 32.0f, fyb);
        iy = fminf(fmaxf(iy, -1.0f), 64.0f);

        float x0f = floorf(ix), y0f = floorf(iy);
        float wx = ix - x0f,    wy = iy - y0f;
        int x0 = (int)x0f, y0 = (int)y0f;           // x0 in [-1,63], y0 in [-1,64]

        float wx1 = 1.0f - wx, wy1 = 1.0f - wy;
        const __half2 W00 = __float2half2_rn(wx1 * wy1);
        const __half2 W01 = __float2half2_rn(wx * wy1);
        const __half2 W10 = __float2half2_rn(wx1 * wy);
        const __half2 W11 = __float2half2_rn(wx * wy);

        // entry index: j*PLANE + (y0+1)*PC + (x0+1) -> always in-bounds
        int e = j * PLANE + y0 * PC + x0 + (PC + 1);
        const __half* pp = imgb + ((size_t)e << 4);   // e * 16 halves

        const uint2 u00 = *reinterpret_cast<const uint2*>(pp);
        const uint2 u01 = *reinterpret_cast<const uint2*>(pp + Cn);
        const uint2 u10 = *reinterpret_cast<const uint2*>(pp + PC * Cn);
        const uint2 u11 = *reinterpret_cast<const uint2*>(pp + (PC + 1) * Cn);

        // packed bilinear blend: channels {0,1} and {2,3}
        __half2 ra = __hmul2(as_h2(u00.x), W00);
        ra = __hfma2(as_h2(u01.x), W01, ra);
        ra = __hfma2(as_h2(u10.x), W10, ra);
        ra = __hfma2(as_h2(u11.x), W11, ra);
        __half2 rb = __hmul2(as_h2(u00.y), W00);
        rb = __hfma2(as_h2(u01.y), W01, rb);
        rb = __hfma2(as_h2(u10.y), W10, rb);
        rb = __hfma2(as_h2(u11.y), W11, rb);

        float2 fa = __half22float2(ra);
        float2 fb = __half22float2(rb);
        acc0 += fa.x;
        acc1 += fa.y;
        acc2 += fb.x;
        acc3 += fb.y;
    }

    // out[b,i,c,h,w]: this lane owns channels 4*cg .. 4*cg+3
    float* op = out + (size_t)bi * Cn * HW + (size_t)(cg * 4) * HW + hw;
    op[0 * HW] = acc0;
    op[1 * HW] = acc1;
    op[2 * HW] = acc2;
    op[3 * HW] = acc3;
}

extern "C" void kernel_launch(void* const* d_in, const int* in_sizes, int n_in,
                              void* d_out, int out_size) {
    const float* flows  = (const float*)d_in[0];   // (B,L,2,H,W)
    const float* images = (const float*)d_in[1];   // (B,L,C,H,W)
    float* out = (float*)d_out;                    // (B,L,C,H,W)

    const int nT = 2 * Bn * Ln * HW;       // 262144 transpose threads
    transpose_kernel<<<(nT + 255) / 256, 256>>>(images);

    gridsample_pscan_kernel<<<2048, 256>>>(flows, out);
}